// round 3
// baseline (speedup 1.0000x reference)
#include <cuda_runtime.h>

// out[r] = (sum over 1024 elems of row r of x) * (sum of coeffs)
// x: (16, 4096, 1024) fp32 -> 65536 rows of 1024
// coeffs: (10, 1) fp32
// One warp per row; each lane loads 8 float4 (128B) coalesced.

__global__ __launch_bounds__(256) void spline_rowsum_kernel(
    const float* __restrict__ x,
    const float* __restrict__ coeffs,
    int n_coeffs,
    float* __restrict__ out,
    int nrows)
{
    int gwarp = (blockIdx.x * blockDim.x + threadIdx.x) >> 5;
    int lane  = threadIdx.x & 31;
    if (gwarp >= nrows) return;

    const float4* row = reinterpret_cast<const float4*>(x) + (size_t)gwarp * 256;

    float s = 0.0f;
#pragma unroll
    for (int k = 0; k < 8; k++) {
        float4 v = row[lane + k * 32];
        s += (v.x + v.y) + (v.z + v.w);
    }

    // butterfly warp reduction
#pragma unroll
    for (int off = 16; off; off >>= 1)
        s += __shfl_xor_sync(0xFFFFFFFFu, s, off);

    if (lane == 0) {
        float c = 0.0f;
        for (int i = 0; i < n_coeffs; i++) c += coeffs[i];
        out[gwarp] = s * c;
    }
}

extern "C" void kernel_launch(void* const* d_in, const int* in_sizes, int n_in,
                              void* d_out, int out_size)
{
    const float* x      = (const float*)d_in[0];
    const float* coeffs = (const float*)d_in[1];
    float* out          = (float*)d_out;

    int nrows    = in_sizes[0] / 1024;   // 65536
    int n_coeffs = in_sizes[1];          // 10

    // 8 warps (rows) per 256-thread block
    int blocks = (nrows + 7) / 8;
    spline_rowsum_kernel<<<blocks, 256>>>(x, coeffs, n_coeffs, out, nrows);
}